// round 13
// baseline (speedup 1.0000x reference)
#include <cuda_runtime.h>
#include <cuda_fp16.h>
#include <cstdint>

// ----------------------------------------------------------------------------
// Round 13: fp16 GEMM, warp tile 64x64, fragment double-buffering in-chunk,
// fused prep conversion.
//   B = fp16(W) + scattered deltas (half atomics);  A = fp16(x)
//   out = A @ B^T + bias (fp32 accum)
// CTA 128x128, 128 threads (warp grid 2x2), BK=64, 3-stage cp.async pipeline,
// 128B-row swizzle.
// ----------------------------------------------------------------------------

#define BM 128
#define BN 128
#define BK 64
#define STAGES 3
#define KK 4096
#define TILE_BYTES (128 * 128)                // 16384
#define STAGE_BYTES (2 * TILE_BYTES)          // 32768
#define SMEM_TOTAL (STAGES * STAGE_BYTES)     // 98304

__device__ __half  g_A[8192u * 4096u];        // 64 MB
__device__ __half  g_B[4096u * 4096u];        // 32 MB

// ---------------- helpers ----------------

__device__ __forceinline__ uint32_t smem_u32(const void* p) {
    uint32_t a;
    asm("{ .reg .u64 t; cvta.to.shared.u64 t, %1; cvt.u32.u64 %0, t; }"
        : "=r"(a) : "l"(p));
    return a;
}

// 128B-row swizzle: 16B chunk c (0..7) in row -> c ^ (row & 7).
__device__ __forceinline__ uint32_t swz(int row, int ch) {
    return (uint32_t)(row * 128 + ((ch ^ (row & 7)) << 4));
}

__device__ __forceinline__ void cp_async16(uint32_t dst, const void* src) {
    asm volatile("cp.async.cg.shared.global [%0], [%1], 16;"
                 :: "r"(dst), "l"(src) : "memory");
}
#define CP_COMMIT() asm volatile("cp.async.commit_group;" ::: "memory")
#define CP_WAIT(n)  asm volatile("cp.async.wait_group %0;" :: "n"(n) : "memory")

__device__ __forceinline__ void ldmatrix4(uint32_t* r, uint32_t addr) {
    asm volatile("ldmatrix.sync.aligned.m8n8.x4.shared.b16 {%0,%1,%2,%3}, [%4];"
                 : "=r"(r[0]), "=r"(r[1]), "=r"(r[2]), "=r"(r[3]) : "r"(addr));
}

__device__ __forceinline__ void mma16816(float* d, const uint32_t* a,
                                         const uint32_t* b) {
    asm volatile(
        "mma.sync.aligned.m16n8k16.row.col.f32.f16.f16.f32 "
        "{%0,%1,%2,%3}, {%4,%5,%6,%7}, {%8,%9}, {%0,%1,%2,%3};"
        : "+f"(d[0]), "+f"(d[1]), "+f"(d[2]), "+f"(d[3])
        : "r"(a[0]), "r"(a[1]), "r"(a[2]), "r"(a[3]), "r"(b[0]), "r"(b[1]));
}

// ---------------- Phase 1 ----------------

// Fused convert: units [0, nw4) -> W->g_B ; [nw4, nw4+nx4) -> x->g_A.
__global__ void prep_conv_kernel(const float* __restrict__ w,
                                 const float* __restrict__ x,
                                 int nw4, int ntot4) {
    for (int i = blockIdx.x * blockDim.x + threadIdx.x; i < ntot4;
         i += gridDim.x * blockDim.x) {
        const float4* src;
        __half2* dst;
        int j;
        if (i < nw4) {
            j = i;
            src = reinterpret_cast<const float4*>(w);
            dst = reinterpret_cast<__half2*>(g_B);
        } else {
            j = i - nw4;
            src = reinterpret_cast<const float4*>(x);
            dst = reinterpret_cast<__half2*>(g_A);
        }
        float4 v = src[j];
        dst[j * 2]     = __halves2half2(__float2half_rn(v.x), __float2half_rn(v.y));
        dst[j * 2 + 1] = __halves2half2(__float2half_rn(v.z), __float2half_rn(v.w));
    }
}

__global__ void prep_scatter_kernel(const float* __restrict__ sw,
                                    const int* __restrict__ rows,
                                    const int* __restrict__ cols,
                                    int nnz, int K) {
    int i = blockIdx.x * blockDim.x + threadIdx.x;
    if (i < nnz)
        atomicAdd(&g_B[(size_t)rows[i] * K + cols[i]], __float2half_rn(sw[i]));
}

// ---------------- Phase 2: GEMM ----------------
// Stage layout: [A | B], each 128 rows x 128B swizzled.

__device__ __forceinline__ void load_stage(uint32_t stage_base, int tid,
                                           const __half* gA,
                                           const __half* gB, int k0) {
    #pragma unroll
    for (int t = 0; t < 2; t++) {
        const __half* src_base = t ? gB : gA;
        const uint32_t dbase = stage_base + t * TILE_BYTES;
        #pragma unroll
        for (int i = 0; i < 8; i++) {
            int u = i * 128 + tid;
            int row = u >> 3, ch = u & 7;
            cp_async16(dbase + swz(row, ch),
                       src_base + (size_t)row * KK + k0 + ch * 8);
        }
    }
}

__global__ __launch_bounds__(128, 2)
void gemm_kernel(const float* __restrict__ bias, float* __restrict__ C, int N) {
    extern __shared__ char smem[];
    const uint32_t sbase = smem_u32(smem);

    const int tid = threadIdx.x;
    const int warp = tid >> 5;
    const int lane = tid & 31;
    const int warp_m = warp & 1;     // 2 (m) x 2 (n), warp tile 64x64
    const int warp_n = warp >> 1;

    const int m0 = blockIdx.y * BM;
    const int n0 = blockIdx.x * BN;

    const __half* gA = g_A + (size_t)m0 * KK;
    const __half* gB = g_B + (size_t)n0 * KK;

    const int a_row = warp_m * 64 + (lane & 15);
    const int a_chb = lane >> 4;                               // k-half bit
    const int b_row = warp_n * 64 + ((lane >> 4) << 3) + (lane & 7);
    const int b_ch  = (lane >> 3) & 1;

    float acc[4][8][4] = {};   // 128 regs
    uint32_t af[2][4][4], bf[2][4][4];   // double-buffered fragments

    // Prologue: stages 0,1
    #pragma unroll
    for (int s = 0; s < STAGES - 1; s++) {
        load_stage(sbase + s * STAGE_BYTES, tid, gA, gB, s * BK);
        CP_COMMIT();
    }

    const int NT = KK / BK;   // 64 chunks
    int s_cur = 0;
    for (int kt = 0; kt < NT; kt++) {
        CP_WAIT(1);           // stage kt ready; kt+1 may still fly
        __syncthreads();

        const int pf = kt + STAGES - 1;
        if (pf < NT) {
            int s_nxt = s_cur + STAGES - 1;
            if (s_nxt >= STAGES) s_nxt -= STAGES;
            load_stage(sbase + s_nxt * STAGE_BYTES, tid, gA, gB, pf * BK);
        }
        CP_COMMIT();

        const uint32_t Ah = sbase + s_cur * STAGE_BYTES;
        const uint32_t Bh = Ah + TILE_BYTES;

        // Preload ks=0 fragments
        #pragma unroll
        for (int bi = 0; bi < 4; bi++)
            ldmatrix4(bf[0][bi], Bh + swz(b_row + bi * 16, b_ch));
        #pragma unroll
        for (int mi = 0; mi < 4; mi++)
            ldmatrix4(af[0][mi], Ah + swz(a_row + mi * 16, a_chb));

        #pragma unroll
        for (int ks = 0; ks < 4; ks++) {     // 4 x k16 per chunk
            const int cur = ks & 1;
            const int nxt = cur ^ 1;
            // Prefetch ks+1 fragments before computing on ks
            if (ks < 3) {
                #pragma unroll
                for (int bi = 0; bi < 4; bi++)
                    ldmatrix4(bf[nxt][bi],
                              Bh + swz(b_row + bi * 16, (ks + 1) * 2 + b_ch));
                #pragma unroll
                for (int mi = 0; mi < 4; mi++)
                    ldmatrix4(af[nxt][mi],
                              Ah + swz(a_row + mi * 16, (ks + 1) * 2 + a_chb));
            }
            #pragma unroll
            for (int mi = 0; mi < 4; mi++) {
                #pragma unroll
                for (int ni = 0; ni < 8; ni++)
                    mma16816(acc[mi][ni], af[cur][mi],
                             &bf[cur][ni >> 1][(ni & 1) * 2]);
            }
        }

        if (++s_cur == STAGES) s_cur = 0;
    }

    // Epilogue
    const int l4 = lane >> 2;
    const int l2 = (lane & 3) * 2;
    #pragma unroll
    for (int ni = 0; ni < 8; ni++) {
        const int col = n0 + warp_n * 64 + ni * 8 + l2;
        const float2 bv = *reinterpret_cast<const float2*>(&bias[col]);
        #pragma unroll
        for (int mi = 0; mi < 4; mi++) {
            const int row = m0 + warp_m * 64 + mi * 16 + l4;
            float2 v0, v1;
            v0.x = acc[mi][ni][0] + bv.x;
            v0.y = acc[mi][ni][1] + bv.y;
            v1.x = acc[mi][ni][2] + bv.x;
            v1.y = acc[mi][ni][3] + bv.y;
            *reinterpret_cast<float2*>(&C[(size_t)row * N + col]) = v0;
            *reinterpret_cast<float2*>(&C[(size_t)(row + 8) * N + col]) = v1;
        }
    }
}

// ---------------- launch ----------------

extern "C" void kernel_launch(void* const* d_in, const int* in_sizes, int n_in,
                              void* d_out, int out_size) {
    const float* x    = (const float*)d_in[0];
    const float* w    = (const float*)d_in[1];
    const float* bias = (const float*)d_in[2];
    const float* sw   = (const float*)d_in[3];
    const int*   idx  = (const int*)d_in[4];
    float* out = (float*)d_out;

    const int N = in_sizes[2];        // 4096
    const int K = in_sizes[1] / N;    // 4096
    const int M = in_sizes[0] / K;    // 8192
    const int nnz = in_sizes[3];      // 262144

    static bool attr_done = false;
    if (!attr_done) {
        cudaFuncSetAttribute(gemm_kernel,
                             cudaFuncAttributeMaxDynamicSharedMemorySize, SMEM_TOTAL);
        attr_done = true;
    }

    const int nw4 = (N * K) / 4;
    const int nx4 = (M / 4) * K;
    prep_conv_kernel<<<3072, 256>>>(w, x, nw4, nw4 + nx4);
    prep_scatter_kernel<<<(nnz + 255) / 256, 256>>>(sw, idx, idx + nnz, nnz, K);

    dim3 grid(N / BN, M / BM);   // (32, 64)
    gemm_kernel<<<grid, 128, SMEM_TOTAL>>>(bias, out, N);
}

// round 14
// speedup vs baseline: 1.0278x; 1.0278x over previous
#include <cuda_runtime.h>
#include <cuda_fp16.h>
#include <cstdint>

// ----------------------------------------------------------------------------
// Round 14: round-12 GEMM (best measured: tensor 80.7%, 560us) + fused prep
// (round-13's one win: 48us). Fragment double-buffering reverted (it cost
// +27us via register pressure at 224 regs).
//   B = fp16(W) + scattered deltas (half atomics);  A = fp16(x)
//   out = A @ B^T + bias (fp32 accum)
// CTA 128x128, 128 threads (warp grid 2x2, warp tile 64x64), BK=64,
// 3-stage cp.async pipeline, 128B-row swizzle.
// ----------------------------------------------------------------------------

#define BM 128
#define BN 128
#define BK 64
#define STAGES 3
#define KK 4096
#define TILE_BYTES (128 * 128)                // 16384
#define STAGE_BYTES (2 * TILE_BYTES)          // 32768
#define SMEM_TOTAL (STAGES * STAGE_BYTES)     // 98304

__device__ __half  g_A[8192u * 4096u];        // 64 MB
__device__ __half  g_B[4096u * 4096u];        // 32 MB

// ---------------- helpers ----------------

__device__ __forceinline__ uint32_t smem_u32(const void* p) {
    uint32_t a;
    asm("{ .reg .u64 t; cvta.to.shared.u64 t, %1; cvt.u32.u64 %0, t; }"
        : "=r"(a) : "l"(p));
    return a;
}

// 128B-row swizzle: 16B chunk c (0..7) in row -> c ^ (row & 7).
__device__ __forceinline__ uint32_t swz(int row, int ch) {
    return (uint32_t)(row * 128 + ((ch ^ (row & 7)) << 4));
}

__device__ __forceinline__ void cp_async16(uint32_t dst, const void* src) {
    asm volatile("cp.async.cg.shared.global [%0], [%1], 16;"
                 :: "r"(dst), "l"(src) : "memory");
}
#define CP_COMMIT() asm volatile("cp.async.commit_group;" ::: "memory")
#define CP_WAIT(n)  asm volatile("cp.async.wait_group %0;" :: "n"(n) : "memory")

__device__ __forceinline__ void ldmatrix4(uint32_t* r, uint32_t addr) {
    asm volatile("ldmatrix.sync.aligned.m8n8.x4.shared.b16 {%0,%1,%2,%3}, [%4];"
                 : "=r"(r[0]), "=r"(r[1]), "=r"(r[2]), "=r"(r[3]) : "r"(addr));
}

__device__ __forceinline__ void mma16816(float* d, const uint32_t* a,
                                         const uint32_t* b) {
    asm volatile(
        "mma.sync.aligned.m16n8k16.row.col.f32.f16.f16.f32 "
        "{%0,%1,%2,%3}, {%4,%5,%6,%7}, {%8,%9}, {%0,%1,%2,%3};"
        : "+f"(d[0]), "+f"(d[1]), "+f"(d[2]), "+f"(d[3])
        : "r"(a[0]), "r"(a[1]), "r"(a[2]), "r"(a[3]), "r"(b[0]), "r"(b[1]));
}

// ---------------- Phase 1 ----------------

// Fused convert: units [0, nw4) -> W->g_B ; [nw4, nw4+nx4) -> x->g_A.
__global__ void prep_conv_kernel(const float* __restrict__ w,
                                 const float* __restrict__ x,
                                 int nw4, int ntot4) {
    for (int i = blockIdx.x * blockDim.x + threadIdx.x; i < ntot4;
         i += gridDim.x * blockDim.x) {
        const float4* src;
        __half2* dst;
        int j;
        if (i < nw4) {
            j = i;
            src = reinterpret_cast<const float4*>(w);
            dst = reinterpret_cast<__half2*>(g_B);
        } else {
            j = i - nw4;
            src = reinterpret_cast<const float4*>(x);
            dst = reinterpret_cast<__half2*>(g_A);
        }
        float4 v = src[j];
        dst[j * 2]     = __halves2half2(__float2half_rn(v.x), __float2half_rn(v.y));
        dst[j * 2 + 1] = __halves2half2(__float2half_rn(v.z), __float2half_rn(v.w));
    }
}

__global__ void prep_scatter_kernel(const float* __restrict__ sw,
                                    const int* __restrict__ rows,
                                    const int* __restrict__ cols,
                                    int nnz, int K) {
    int i = blockIdx.x * blockDim.x + threadIdx.x;
    if (i < nnz)
        atomicAdd(&g_B[(size_t)rows[i] * K + cols[i]], __float2half_rn(sw[i]));
}

// ---------------- Phase 2: GEMM ----------------
// Stage layout: [A | B], each 128 rows x 128B swizzled.

__device__ __forceinline__ void load_stage(uint32_t stage_base, int tid,
                                           const __half* gA,
                                           const __half* gB, int k0) {
    #pragma unroll
    for (int t = 0; t < 2; t++) {
        const __half* src_base = t ? gB : gA;
        const uint32_t dbase = stage_base + t * TILE_BYTES;
        #pragma unroll
        for (int i = 0; i < 8; i++) {
            int u = i * 128 + tid;
            int row = u >> 3, ch = u & 7;
            cp_async16(dbase + swz(row, ch),
                       src_base + (size_t)row * KK + k0 + ch * 8);
        }
    }
}

__global__ __launch_bounds__(128, 2)
void gemm_kernel(const float* __restrict__ bias, float* __restrict__ C, int N) {
    extern __shared__ char smem[];
    const uint32_t sbase = smem_u32(smem);

    const int tid = threadIdx.x;
    const int warp = tid >> 5;
    const int lane = tid & 31;
    const int warp_m = warp & 1;     // 2 (m) x 2 (n), warp tile 64x64
    const int warp_n = warp >> 1;

    const int m0 = blockIdx.y * BM;
    const int n0 = blockIdx.x * BN;

    const __half* gA = g_A + (size_t)m0 * KK;
    const __half* gB = g_B + (size_t)n0 * KK;

    const int a_row = warp_m * 64 + (lane & 15);
    const int a_chb = lane >> 4;                               // k-half bit
    const int b_row = warp_n * 64 + ((lane >> 4) << 3) + (lane & 7);
    const int b_ch  = (lane >> 3) & 1;

    float acc[4][8][4] = {};   // 128 regs

    // Prologue: stages 0,1
    #pragma unroll
    for (int s = 0; s < STAGES - 1; s++) {
        load_stage(sbase + s * STAGE_BYTES, tid, gA, gB, s * BK);
        CP_COMMIT();
    }

    const int NT = KK / BK;   // 64 chunks
    int s_cur = 0;
    for (int kt = 0; kt < NT; kt++) {
        CP_WAIT(1);           // stage kt ready; kt+1 may still fly
        __syncthreads();

        const int pf = kt + STAGES - 1;
        if (pf < NT) {
            int s_nxt = s_cur + STAGES - 1;
            if (s_nxt >= STAGES) s_nxt -= STAGES;
            load_stage(sbase + s_nxt * STAGE_BYTES, tid, gA, gB, pf * BK);
        }
        CP_COMMIT();

        const uint32_t Ah = sbase + s_cur * STAGE_BYTES;
        const uint32_t Bh = Ah + TILE_BYTES;

        #pragma unroll
        for (int ks = 0; ks < 4; ks++) {     // 4 x k16 per chunk
            uint32_t af[4][4], bf[4][4];
            #pragma unroll
            for (int bi = 0; bi < 4; bi++)
                ldmatrix4(bf[bi], Bh + swz(b_row + bi * 16, ks * 2 + b_ch));
            #pragma unroll
            for (int mi = 0; mi < 4; mi++)
                ldmatrix4(af[mi], Ah + swz(a_row + mi * 16, ks * 2 + a_chb));

            #pragma unroll
            for (int mi = 0; mi < 4; mi++) {
                #pragma unroll
                for (int ni = 0; ni < 8; ni++)
                    mma16816(acc[mi][ni], af[mi], &bf[ni >> 1][(ni & 1) * 2]);
            }
        }

        if (++s_cur == STAGES) s_cur = 0;
    }

    // Epilogue
    const int l4 = lane >> 2;
    const int l2 = (lane & 3) * 2;
    #pragma unroll
    for (int ni = 0; ni < 8; ni++) {
        const int col = n0 + warp_n * 64 + ni * 8 + l2;
        const float2 bv = *reinterpret_cast<const float2*>(&bias[col]);
        #pragma unroll
        for (int mi = 0; mi < 4; mi++) {
            const int row = m0 + warp_m * 64 + mi * 16 + l4;
            float2 v0, v1;
            v0.x = acc[mi][ni][0] + bv.x;
            v0.y = acc[mi][ni][1] + bv.y;
            v1.x = acc[mi][ni][2] + bv.x;
            v1.y = acc[mi][ni][3] + bv.y;
            *reinterpret_cast<float2*>(&C[(size_t)row * N + col]) = v0;
            *reinterpret_cast<float2*>(&C[(size_t)(row + 8) * N + col]) = v1;
        }
    }
}

// ---------------- launch ----------------

extern "C" void kernel_launch(void* const* d_in, const int* in_sizes, int n_in,
                              void* d_out, int out_size) {
    const float* x    = (const float*)d_in[0];
    const float* w    = (const float*)d_in[1];
    const float* bias = (const float*)d_in[2];
    const float* sw   = (const float*)d_in[3];
    const int*   idx  = (const int*)d_in[4];
    float* out = (float*)d_out;

    const int N = in_sizes[2];        // 4096
    const int K = in_sizes[1] / N;    // 4096
    const int M = in_sizes[0] / K;    // 8192
    const int nnz = in_sizes[3];      // 262144

    static bool attr_done = false;
    if (!attr_done) {
        cudaFuncSetAttribute(gemm_kernel,
                             cudaFuncAttributeMaxDynamicSharedMemorySize, SMEM_TOTAL);
        attr_done = true;
    }

    const int nw4 = (N * K) / 4;
    const int nx4 = (M / 4) * K;
    prep_conv_kernel<<<3072, 256>>>(w, x, nw4, nw4 + nx4);
    prep_scatter_kernel<<<(nnz + 255) / 256, 256>>>(sw, idx, idx + nnz, nnz, K);

    dim3 grid(N / BN, M / BM);   // (32, 64)
    gemm_kernel<<<grid, 128, SMEM_TOTAL>>>(bias, out, N);
}

// round 15
// speedup vs baseline: 1.0278x; 1.0001x over previous
#include <cuda_runtime.h>
#include <cuda_fp16.h>
#include <cstdint>

// ----------------------------------------------------------------------------
// Round 14: round-12 GEMM (best measured: tensor 80.7%, 560us) + fused prep
// (round-13's one win: 48us). Fragment double-buffering reverted (it cost
// +27us via register pressure at 224 regs).
//   B = fp16(W) + scattered deltas (half atomics);  A = fp16(x)
//   out = A @ B^T + bias (fp32 accum)
// CTA 128x128, 128 threads (warp grid 2x2, warp tile 64x64), BK=64,
// 3-stage cp.async pipeline, 128B-row swizzle.
// ----------------------------------------------------------------------------

#define BM 128
#define BN 128
#define BK 64
#define STAGES 3
#define KK 4096
#define TILE_BYTES (128 * 128)                // 16384
#define STAGE_BYTES (2 * TILE_BYTES)          // 32768
#define SMEM_TOTAL (STAGES * STAGE_BYTES)     // 98304

__device__ __half  g_A[8192u * 4096u];        // 64 MB
__device__ __half  g_B[4096u * 4096u];        // 32 MB

// ---------------- helpers ----------------

__device__ __forceinline__ uint32_t smem_u32(const void* p) {
    uint32_t a;
    asm("{ .reg .u64 t; cvta.to.shared.u64 t, %1; cvt.u32.u64 %0, t; }"
        : "=r"(a) : "l"(p));
    return a;
}

// 128B-row swizzle: 16B chunk c (0..7) in row -> c ^ (row & 7).
__device__ __forceinline__ uint32_t swz(int row, int ch) {
    return (uint32_t)(row * 128 + ((ch ^ (row & 7)) << 4));
}

__device__ __forceinline__ void cp_async16(uint32_t dst, const void* src) {
    asm volatile("cp.async.cg.shared.global [%0], [%1], 16;"
                 :: "r"(dst), "l"(src) : "memory");
}
#define CP_COMMIT() asm volatile("cp.async.commit_group;" ::: "memory")
#define CP_WAIT(n)  asm volatile("cp.async.wait_group %0;" :: "n"(n) : "memory")

__device__ __forceinline__ void ldmatrix4(uint32_t* r, uint32_t addr) {
    asm volatile("ldmatrix.sync.aligned.m8n8.x4.shared.b16 {%0,%1,%2,%3}, [%4];"
                 : "=r"(r[0]), "=r"(r[1]), "=r"(r[2]), "=r"(r[3]) : "r"(addr));
}

__device__ __forceinline__ void mma16816(float* d, const uint32_t* a,
                                         const uint32_t* b) {
    asm volatile(
        "mma.sync.aligned.m16n8k16.row.col.f32.f16.f16.f32 "
        "{%0,%1,%2,%3}, {%4,%5,%6,%7}, {%8,%9}, {%0,%1,%2,%3};"
        : "+f"(d[0]), "+f"(d[1]), "+f"(d[2]), "+f"(d[3])
        : "r"(a[0]), "r"(a[1]), "r"(a[2]), "r"(a[3]), "r"(b[0]), "r"(b[1]));
}

// ---------------- Phase 1 ----------------

// Fused convert: units [0, nw4) -> W->g_B ; [nw4, nw4+nx4) -> x->g_A.
__global__ void prep_conv_kernel(const float* __restrict__ w,
                                 const float* __restrict__ x,
                                 int nw4, int ntot4) {
    for (int i = blockIdx.x * blockDim.x + threadIdx.x; i < ntot4;
         i += gridDim.x * blockDim.x) {
        const float4* src;
        __half2* dst;
        int j;
        if (i < nw4) {
            j = i;
            src = reinterpret_cast<const float4*>(w);
            dst = reinterpret_cast<__half2*>(g_B);
        } else {
            j = i - nw4;
            src = reinterpret_cast<const float4*>(x);
            dst = reinterpret_cast<__half2*>(g_A);
        }
        float4 v = src[j];
        dst[j * 2]     = __halves2half2(__float2half_rn(v.x), __float2half_rn(v.y));
        dst[j * 2 + 1] = __halves2half2(__float2half_rn(v.z), __float2half_rn(v.w));
    }
}

__global__ void prep_scatter_kernel(const float* __restrict__ sw,
                                    const int* __restrict__ rows,
                                    const int* __restrict__ cols,
                                    int nnz, int K) {
    int i = blockIdx.x * blockDim.x + threadIdx.x;
    if (i < nnz)
        atomicAdd(&g_B[(size_t)rows[i] * K + cols[i]], __float2half_rn(sw[i]));
}

// ---------------- Phase 2: GEMM ----------------
// Stage layout: [A | B], each 128 rows x 128B swizzled.

__device__ __forceinline__ void load_stage(uint32_t stage_base, int tid,
                                           const __half* gA,
                                           const __half* gB, int k0) {
    #pragma unroll
    for (int t = 0; t < 2; t++) {
        const __half* src_base = t ? gB : gA;
        const uint32_t dbase = stage_base + t * TILE_BYTES;
        #pragma unroll
        for (int i = 0; i < 8; i++) {
            int u = i * 128 + tid;
            int row = u >> 3, ch = u & 7;
            cp_async16(dbase + swz(row, ch),
                       src_base + (size_t)row * KK + k0 + ch * 8);
        }
    }
}

__global__ __launch_bounds__(128, 2)
void gemm_kernel(const float* __restrict__ bias, float* __restrict__ C, int N) {
    extern __shared__ char smem[];
    const uint32_t sbase = smem_u32(smem);

    const int tid = threadIdx.x;
    const int warp = tid >> 5;
    const int lane = tid & 31;
    const int warp_m = warp & 1;     // 2 (m) x 2 (n), warp tile 64x64
    const int warp_n = warp >> 1;

    const int m0 = blockIdx.y * BM;
    const int n0 = blockIdx.x * BN;

    const __half* gA = g_A + (size_t)m0 * KK;
    const __half* gB = g_B + (size_t)n0 * KK;

    const int a_row = warp_m * 64 + (lane & 15);
    const int a_chb = lane >> 4;                               // k-half bit
    const int b_row = warp_n * 64 + ((lane >> 4) << 3) + (lane & 7);
    const int b_ch  = (lane >> 3) & 1;

    float acc[4][8][4] = {};   // 128 regs

    // Prologue: stages 0,1
    #pragma unroll
    for (int s = 0; s < STAGES - 1; s++) {
        load_stage(sbase + s * STAGE_BYTES, tid, gA, gB, s * BK);
        CP_COMMIT();
    }

    const int NT = KK / BK;   // 64 chunks
    int s_cur = 0;
    for (int kt = 0; kt < NT; kt++) {
        CP_WAIT(1);           // stage kt ready; kt+1 may still fly
        __syncthreads();

        const int pf = kt + STAGES - 1;
        if (pf < NT) {
            int s_nxt = s_cur + STAGES - 1;
            if (s_nxt >= STAGES) s_nxt -= STAGES;
            load_stage(sbase + s_nxt * STAGE_BYTES, tid, gA, gB, pf * BK);
        }
        CP_COMMIT();

        const uint32_t Ah = sbase + s_cur * STAGE_BYTES;
        const uint32_t Bh = Ah + TILE_BYTES;

        #pragma unroll
        for (int ks = 0; ks < 4; ks++) {     // 4 x k16 per chunk
            uint32_t af[4][4], bf[4][4];
            #pragma unroll
            for (int bi = 0; bi < 4; bi++)
                ldmatrix4(bf[bi], Bh + swz(b_row + bi * 16, ks * 2 + b_ch));
            #pragma unroll
            for (int mi = 0; mi < 4; mi++)
                ldmatrix4(af[mi], Ah + swz(a_row + mi * 16, ks * 2 + a_chb));

            #pragma unroll
            for (int mi = 0; mi < 4; mi++) {
                #pragma unroll
                for (int ni = 0; ni < 8; ni++)
                    mma16816(acc[mi][ni], af[mi], &bf[ni >> 1][(ni & 1) * 2]);
            }
        }

        if (++s_cur == STAGES) s_cur = 0;
    }

    // Epilogue
    const int l4 = lane >> 2;
    const int l2 = (lane & 3) * 2;
    #pragma unroll
    for (int ni = 0; ni < 8; ni++) {
        const int col = n0 + warp_n * 64 + ni * 8 + l2;
        const float2 bv = *reinterpret_cast<const float2*>(&bias[col]);
        #pragma unroll
        for (int mi = 0; mi < 4; mi++) {
            const int row = m0 + warp_m * 64 + mi * 16 + l4;
            float2 v0, v1;
            v0.x = acc[mi][ni][0] + bv.x;
            v0.y = acc[mi][ni][1] + bv.y;
            v1.x = acc[mi][ni][2] + bv.x;
            v1.y = acc[mi][ni][3] + bv.y;
            *reinterpret_cast<float2*>(&C[(size_t)row * N + col]) = v0;
            *reinterpret_cast<float2*>(&C[(size_t)(row + 8) * N + col]) = v1;
        }
    }
}

// ---------------- launch ----------------

extern "C" void kernel_launch(void* const* d_in, const int* in_sizes, int n_in,
                              void* d_out, int out_size) {
    const float* x    = (const float*)d_in[0];
    const float* w    = (const float*)d_in[1];
    const float* bias = (const float*)d_in[2];
    const float* sw   = (const float*)d_in[3];
    const int*   idx  = (const int*)d_in[4];
    float* out = (float*)d_out;

    const int N = in_sizes[2];        // 4096
    const int K = in_sizes[1] / N;    // 4096
    const int M = in_sizes[0] / K;    // 8192
    const int nnz = in_sizes[3];      // 262144

    static bool attr_done = false;
    if (!attr_done) {
        cudaFuncSetAttribute(gemm_kernel,
                             cudaFuncAttributeMaxDynamicSharedMemorySize, SMEM_TOTAL);
        attr_done = true;
    }

    const int nw4 = (N * K) / 4;
    const int nx4 = (M / 4) * K;
    prep_conv_kernel<<<3072, 256>>>(w, x, nw4, nw4 + nx4);
    prep_scatter_kernel<<<(nnz + 255) / 256, 256>>>(sw, idx, idx + nnz, nnz, K);

    dim3 grid(N / BN, M / BM);   // (32, 64)
    gemm_kernel<<<grid, 128, SMEM_TOTAL>>>(bias, out, N);
}